// round 6
// baseline (speedup 1.0000x reference)
#include <cuda_runtime.h>
#include <cuda_bf16.h>
#include <math.h>
#include <stdint.h>

#define K_COMP 64
#define DDIM   256
#define MU_PAD 264     // bf16/row: 132 words -> ldmatrix rows cover all 32 banks

// dynamic smem layout (bytes)
#define SMU_OFF   0
#define SMU_BYTES (K_COMP * MU_PAD * 2)            // 33792
#define SC_OFF    SMU_BYTES                        // 4 float arrays of 64
#define ST_OFF    (SMU_BYTES + 1024)               // 34816
#define ST_STRIDE 72                               // floats per row (pad: conflict-free)
#define ST_BYTES  (128 * ST_STRIDE * 4)            // 36864
#define SMEM_TOTAL (ST_OFF + ST_BYTES)             // 71680

__device__ __align__(16) __nv_bfloat16 g_mu[K_COMP * DDIM];
__device__ float g_kappa[K_COMP];
__device__ float g_logC[K_COMP];
__device__ float g_la[K_COMP];
__device__ float g_C2[K_COMP];

// ---------------- prep: 32 warps, lane-parallel series + warp-reduced softmax ---------
__global__ void prep_fast(const float* __restrict__ alpha_logit,
                          const float* __restrict__ mu_unnorm,
                          const float* __restrict__ log_kappa) {
    __shared__ float cm[K_COMP];
    __shared__ float sa[K_COMP];
    int tid = threadIdx.x, warp = tid >> 5, lane = tid & 31;
    const float s = 0.5f * (float)DDIM - 1.0f;   // 127

    if (tid < K_COMP) {
        cm[tid] = lgammaf((float)tid + 1.0f) + lgammaf((float)tid + s + 1.0f);
        sa[tid] = alpha_logit[tid];
    }
    __syncthreads();

    float a0 = sa[lane], a1 = sa[lane + 32];
    float amax = fmaxf(a0, a1);
#pragma unroll
    for (int off = 16; off > 0; off >>= 1)
        amax = fmaxf(amax, __shfl_xor_sync(0xffffffffu, amax, off));
    float ae = expf(a0 - amax) + expf(a1 - amax);
#pragma unroll
    for (int off = 16; off > 0; off >>= 1)
        ae += __shfl_xor_sync(0xffffffffu, ae, off);
    float lse_a = amax + logf(ae);

#pragma unroll
    for (int rr = 0; rr < 2; rr++) {
        int k = warp + rr * 32;

        const float4* p = reinterpret_cast<const float4*>(mu_unnorm + (size_t)k * DDIM);
        float4 v1 = p[lane * 2], v2 = p[lane * 2 + 1];
        float sum = v1.x*v1.x + v1.y*v1.y + v1.z*v1.z + v1.w*v1.w
                  + v2.x*v2.x + v2.y*v2.y + v2.z*v2.z + v2.w*v2.w;
#pragma unroll
        for (int off = 16; off > 0; off >>= 1)
            sum += __shfl_xor_sync(0xffffffffu, sum, off);
        float inv = 1.0f / fmaxf(sqrtf(sum), 1e-12f);
        __nv_bfloat162* dst = reinterpret_cast<__nv_bfloat162*>(g_mu + (size_t)k * DDIM);
        dst[lane * 4 + 0] = __float22bfloat162_rn(make_float2(v1.x * inv, v1.y * inv));
        dst[lane * 4 + 1] = __float22bfloat162_rn(make_float2(v1.z * inv, v1.w * inv));
        dst[lane * 4 + 2] = __float22bfloat162_rn(make_float2(v2.x * inv, v2.y * inv));
        dst[lane * 4 + 3] = __float22bfloat162_rn(make_float2(v2.z * inv, v2.w * inv));

        float kappa = expf(log_kappa[k]) + 1e-6f;
        float lk2   = logf(0.5f * kappa);
        float t0 = fmaf(2.0f * lane + s,        lk2, -cm[lane]);
        float t1 = fmaf(2.0f * (lane + 32) + s, lk2, -cm[lane + 32]);
        float tm = fmaxf(t0, t1);
#pragma unroll
        for (int off = 16; off > 0; off >>= 1)
            tm = fmaxf(tm, __shfl_xor_sync(0xffffffffu, tm, off));
        float ts = expf(t0 - tm) + expf(t1 - tm);
#pragma unroll
        for (int off = 16; off > 0; off >>= 1)
            ts += __shfl_xor_sync(0xffffffffu, ts, off);

        if (lane == 0) {
            float lbi  = tm + logf(ts);
            float logC = (float)DDIM * (-0.91893853320467274f) + s * logf(kappa) - lbi;
            float la   = sa[k] - lse_a;
            g_kappa[k] = kappa;
            g_logC[k]  = logC;
            g_la[k]    = la;
            g_C2[k]    = logC + la;
        }
    }
}

// ---------------- fast exp: FFMA-only --------------------------------------------------
__device__ __forceinline__ float fexp(float x) {
    x = fmaxf(x, -87.0f);
    float z = x * 1.4426950408889634f;
    float t = z + 12582912.0f;
    float fi = t - 12582912.0f;
    float f = z - fi;
    int  i  = __float_as_int(t) - 0x4B400000;
    float p = 1.3333558e-3f;
    p = fmaf(p, f, 9.6181291e-3f);
    p = fmaf(p, f, 5.5504109e-2f);
    p = fmaf(p, f, 2.4022651e-1f);
    p = fmaf(p, f, 6.9314718e-1f);
    p = fmaf(p, f, 1.0f);
    return __int_as_float(__float_as_int(p) + (i << 23));
}

__device__ __forceinline__ uint32_t f22bf(float2 v) {
    __nv_bfloat162 b = __float22bfloat162_rn(v);
    return *reinterpret_cast<uint32_t*>(&b);
}

// ---------------- main: R4 mainloop (permuted-k LDG.128 + ldmatrix) -------------------
// + smem-transposed store epilogue: lp tile staged in smem, then streamed to GMEM with
// fully coalesced STG.128 (store wavefronts/CTA 1024 -> 256).
__global__ void __launch_bounds__(256, 3)
vmf_main(const float* __restrict__ x,
         float* __restrict__ out_llh,
         float* __restrict__ out_lp,
         int N) {
    extern __shared__ char smem[];
    __nv_bfloat16* smu = reinterpret_cast<__nv_bfloat16*>(smem + SMU_OFF);
    float* s_kappa = reinterpret_cast<float*>(smem + SC_OFF);
    float* s_logC  = s_kappa + K_COMP;
    float* s_la    = s_logC + K_COMP;
    float* s_C2    = s_la   + K_COMP;
    float* sT      = reinterpret_cast<float*>(smem + ST_OFF);   // [128][72]

    int tid = threadIdx.x;
    uint32_t smem_u32 = (uint32_t)__cvta_generic_to_shared(smem);

    // stage mu with k-pair permutation (smem slot i <- phys pair (i<4 ? 2i : 2i-7))
    const uint32_t* gmu32 = reinterpret_cast<const uint32_t*>(g_mu);
    for (int idx = tid; idx < K_COMP * (DDIM / 2); idx += 256) {
        int kk = idx >> 7;
        int dp = idx & 127;
        int i  = dp & 7;
        int srcp = (i < 4) ? (2 * i) : (2 * i - 7);
        int src  = (dp & ~7) | srcp;
        reinterpret_cast<uint32_t*>(smu + (size_t)kk * MU_PAD)[dp] = gmu32[kk * 128 + src];
    }
    if (tid < K_COMP) {
        s_kappa[tid] = g_kappa[tid];
        s_logC[tid]  = g_logC[tid];
        s_la[tid]    = g_la[tid];
        s_C2[tid]    = g_C2[tid];
    }
    __syncthreads();

    int warp = tid >> 5, lane = tid & 31;
    int blockRow0 = blockIdx.x * 128;
    int row0 = blockRow0 + warp * 16;

    int r  = lane >> 2;        // 0..7
    int cq = (lane & 3) * 2;   // logical col-pair base

    const float* p0 = x + (size_t)(row0 + r) * DDIM + (lane & 3) * 4;
    const float* p1 = p0 + 8 * DDIM;

    // ldmatrix B lane address (reads permuted smu)
    int li   = lane & 7;
    int csel = (lane >> 3) & 1;
    int tsel = (lane >> 4) & 1;
    uint32_t lm_base = smem_u32 + SMU_OFF
                     + (uint32_t)(((li + tsel * 8) * MU_PAD + csel * 8) * 2);

    float acc[8][4];
#pragma unroll
    for (int t = 0; t < 8; t++)
#pragma unroll
        for (int j = 0; j < 4; j++) acc[t][j] = 0.0f;

    // depth-2 prefetch, 3 rotating buffers of 2 float4
    float4 buf[3][2];
#pragma unroll
    for (int g = 0; g < 2; g++) {
        buf[g][0] = __ldcs(reinterpret_cast<const float4*>(p0 + g * 16));
        buf[g][1] = __ldcs(reinterpret_cast<const float4*>(p1 + g * 16));
    }

#pragma unroll
    for (int kk = 0; kk < 16; kk++) {
        int cs = kk % 3;
        if (kk < 14) {
            int ns = (kk + 2) % 3;
            int off = (kk + 2) * 16;
            buf[ns][0] = __ldcs(reinterpret_cast<const float4*>(p0 + off));
            buf[ns][1] = __ldcs(reinterpret_cast<const float4*>(p1 + off));
        }
        float4 A0 = buf[cs][0], A1 = buf[cs][1];
        uint32_t fa0 = f22bf(make_float2(A0.x, A0.y));
        uint32_t fa2 = f22bf(make_float2(A0.z, A0.w));
        uint32_t fa1 = f22bf(make_float2(A1.x, A1.y));
        uint32_t fa3 = f22bf(make_float2(A1.z, A1.w));

        uint32_t lmaddr = lm_base + (uint32_t)(kk * 32);
#pragma unroll
        for (int tp = 0; tp < 4; tp++) {
            uint32_t b0, b1, b2, b3;
            asm volatile(
                "ldmatrix.sync.aligned.m8n8.x4.shared.b16 {%0,%1,%2,%3}, [%4];\n"
                : "=r"(b0), "=r"(b1), "=r"(b2), "=r"(b3)
                : "r"(lmaddr + (uint32_t)(tp * 16 * MU_PAD * 2)));
            asm volatile(
                "mma.sync.aligned.m16n8k16.row.col.f32.bf16.bf16.f32 "
                "{%0,%1,%2,%3}, {%4,%5,%6,%7}, {%8,%9}, {%0,%1,%2,%3};\n"
                : "+f"(acc[tp*2][0]), "+f"(acc[tp*2][1]), "+f"(acc[tp*2][2]), "+f"(acc[tp*2][3])
                : "r"(fa0), "r"(fa1), "r"(fa2), "r"(fa3), "r"(b0), "r"(b1));
            asm volatile(
                "mma.sync.aligned.m16n8k16.row.col.f32.bf16.bf16.f32 "
                "{%0,%1,%2,%3}, {%4,%5,%6,%7}, {%8,%9}, {%0,%1,%2,%3};\n"
                : "+f"(acc[tp*2+1][0]), "+f"(acc[tp*2+1][1]), "+f"(acc[tp*2+1][2]), "+f"(acc[tp*2+1][3])
                : "r"(fa0), "r"(fa1), "r"(fa2), "r"(fa3), "r"(b2), "r"(b3));
        }
    }

    // ---- epilogue: lp -> smem transpose buffer; logsumexp from registers ----
    int rl0 = warp * 16 + r;              // local rows rl0, rl0+8
    float* st0 = sT + rl0 * ST_STRIDE;
    float* st1 = sT + (rl0 + 8) * ST_STRIDE;

    float m0 = -1e30f, m1 = -1e30f;
#pragma unroll
    for (int t = 0; t < 8; t++) {
        int cc = t * 8 + cq;
        float k0 = s_kappa[cc], k1 = s_kappa[cc + 1];
        float lc0 = s_logC[cc], lc1 = s_logC[cc + 1];
        float la0 = s_la[cc],   la1 = s_la[cc + 1];
        float lp00 = fmaf(k0, acc[t][0], lc0);
        float lp01 = fmaf(k1, acc[t][1], lc1);
        float lp10 = fmaf(k0, acc[t][2], lc0);
        float lp11 = fmaf(k1, acc[t][3], lc1);
        *reinterpret_cast<float2*>(st0 + cc) = make_float2(lp00, lp01);
        *reinterpret_cast<float2*>(st1 + cc) = make_float2(lp10, lp11);
        m0 = fmaxf(m0, fmaxf(lp00 + la0, lp01 + la1));
        m1 = fmaxf(m1, fmaxf(lp10 + la0, lp11 + la1));
    }
    m0 = fmaxf(m0, __shfl_xor_sync(0xffffffffu, m0, 1));
    m0 = fmaxf(m0, __shfl_xor_sync(0xffffffffu, m0, 2));
    m1 = fmaxf(m1, __shfl_xor_sync(0xffffffffu, m1, 1));
    m1 = fmaxf(m1, __shfl_xor_sync(0xffffffffu, m1, 2));

    float s0 = 0.0f, s1 = 0.0f;
#pragma unroll
    for (int t = 0; t < 8; t++) {
        int cc = t * 8 + cq;
        float k0 = s_kappa[cc], k1 = s_kappa[cc + 1];
        float c20 = s_C2[cc],   c21 = s_C2[cc + 1];
        s0 += fexp(fmaf(k0, acc[t][0], c20) - m0);
        s0 += fexp(fmaf(k1, acc[t][1], c21) - m0);
        s1 += fexp(fmaf(k0, acc[t][2], c20) - m1);
        s1 += fexp(fmaf(k1, acc[t][3], c21) - m1);
    }
    s0 += __shfl_xor_sync(0xffffffffu, s0, 1);
    s0 += __shfl_xor_sync(0xffffffffu, s0, 2);
    s1 += __shfl_xor_sync(0xffffffffu, s1, 1);
    s1 += __shfl_xor_sync(0xffffffffu, s1, 2);

    if ((lane & 3) == 0) {
        out_llh[row0 + r]     = m0 + __logf(s0);
        out_llh[row0 + r + 8] = m1 + __logf(s1);
    }

    __syncthreads();

    // ---- coalesced stream: smem tile -> out_lp (contiguous 32KB per CTA) ----
    float* outp = out_lp + (size_t)blockRow0 * K_COMP;
#pragma unroll
    for (int it = 0; it < 8; it++) {
        int idx = it * 256 + tid;          // float4 index within tile (0..2047)
        int row = idx >> 4;
        int ch  = idx & 15;
        float4 v = *reinterpret_cast<const float4*>(sT + row * ST_STRIDE + ch * 4);
        __stcs(reinterpret_cast<float4*>(outp) + idx, v);
    }
}

// ---------------- launch -----------------------------------------------------------
extern "C" void kernel_launch(void* const* d_in, const int* in_sizes, int n_in,
                              void* d_out, int out_size) {
    const float* x           = (const float*)d_in[0];
    const float* alpha_logit = (const float*)d_in[1];
    const float* mu_unnorm   = (const float*)d_in[2];
    const float* log_kappa   = (const float*)d_in[3];

    int K = in_sizes[1];            // 64
    int D = in_sizes[2] / K;        // 256
    int N = in_sizes[0] / D;        // 262144
    (void)K; (void)n_in; (void)out_size;

    float* out = (float*)d_out;
    float* llh = out;               // (N,)
    float* lp  = out + (size_t)N;   // (N, K) row-major

    cudaFuncSetAttribute(vmf_main, cudaFuncAttributeMaxDynamicSharedMemorySize, SMEM_TOTAL);

    prep_fast<<<1, 1024>>>(alpha_logit, mu_unnorm, log_kappa);
    vmf_main<<<N / 128, 256, SMEM_TOTAL>>>(x, llh, lp, N);
}

// round 7
// speedup vs baseline: 1.2718x; 1.2718x over previous
#include <cuda_runtime.h>
#include <cuda_bf16.h>
#include <math.h>
#include <stdint.h>

#define K_COMP 64
#define DDIM   256
#define MU_PAD 264     // bf16/row: 132 words -> ldmatrix rows cover all 32 banks

__device__ __align__(16) __nv_bfloat16 g_mu[K_COMP * DDIM];
__device__ float g_kappa[K_COMP];
__device__ float g_logC[K_COMP];
__device__ float g_la[K_COMP];
__device__ float g_C2[K_COMP];

// ---------------- prep: 32 warps, lane-parallel series + warp-reduced softmax ---------
__global__ void prep_fast(const float* __restrict__ alpha_logit,
                          const float* __restrict__ mu_unnorm,
                          const float* __restrict__ log_kappa) {
    __shared__ float cm[K_COMP];
    __shared__ float sa[K_COMP];
    int tid = threadIdx.x, warp = tid >> 5, lane = tid & 31;
    const float s = 0.5f * (float)DDIM - 1.0f;   // 127

    if (tid < K_COMP) {
        cm[tid] = lgammaf((float)tid + 1.0f) + lgammaf((float)tid + s + 1.0f);
        sa[tid] = alpha_logit[tid];
    }
    __syncthreads();

    float a0 = sa[lane], a1 = sa[lane + 32];
    float amax = fmaxf(a0, a1);
#pragma unroll
    for (int off = 16; off > 0; off >>= 1)
        amax = fmaxf(amax, __shfl_xor_sync(0xffffffffu, amax, off));
    float ae = expf(a0 - amax) + expf(a1 - amax);
#pragma unroll
    for (int off = 16; off > 0; off >>= 1)
        ae += __shfl_xor_sync(0xffffffffu, ae, off);
    float lse_a = amax + logf(ae);

#pragma unroll
    for (int rr = 0; rr < 2; rr++) {
        int k = warp + rr * 32;

        const float4* p = reinterpret_cast<const float4*>(mu_unnorm + (size_t)k * DDIM);
        float4 v1 = p[lane * 2], v2 = p[lane * 2 + 1];
        float sum = v1.x*v1.x + v1.y*v1.y + v1.z*v1.z + v1.w*v1.w
                  + v2.x*v2.x + v2.y*v2.y + v2.z*v2.z + v2.w*v2.w;
#pragma unroll
        for (int off = 16; off > 0; off >>= 1)
            sum += __shfl_xor_sync(0xffffffffu, sum, off);
        float inv = 1.0f / fmaxf(sqrtf(sum), 1e-12f);
        __nv_bfloat162* dst = reinterpret_cast<__nv_bfloat162*>(g_mu + (size_t)k * DDIM);
        dst[lane * 4 + 0] = __float22bfloat162_rn(make_float2(v1.x * inv, v1.y * inv));
        dst[lane * 4 + 1] = __float22bfloat162_rn(make_float2(v1.z * inv, v1.w * inv));
        dst[lane * 4 + 2] = __float22bfloat162_rn(make_float2(v2.x * inv, v2.y * inv));
        dst[lane * 4 + 3] = __float22bfloat162_rn(make_float2(v2.z * inv, v2.w * inv));

        float kappa = expf(log_kappa[k]) + 1e-6f;
        float lk2   = logf(0.5f * kappa);
        float t0 = fmaf(2.0f * lane + s,        lk2, -cm[lane]);
        float t1 = fmaf(2.0f * (lane + 32) + s, lk2, -cm[lane + 32]);
        float tm = fmaxf(t0, t1);
#pragma unroll
        for (int off = 16; off > 0; off >>= 1)
            tm = fmaxf(tm, __shfl_xor_sync(0xffffffffu, tm, off));
        float ts = expf(t0 - tm) + expf(t1 - tm);
#pragma unroll
        for (int off = 16; off > 0; off >>= 1)
            ts += __shfl_xor_sync(0xffffffffu, ts, off);

        if (lane == 0) {
            float lbi  = tm + logf(ts);
            float logC = (float)DDIM * (-0.91893853320467274f) + s * logf(kappa) - lbi;
            float la   = sa[k] - lse_a;
            g_kappa[k] = kappa;
            g_logC[k]  = logC;
            g_la[k]    = la;
            g_C2[k]    = logC + la;
        }
    }
}

// ---------------- fast exp: FFMA-only --------------------------------------------------
__device__ __forceinline__ float fexp(float x) {
    x = fmaxf(x, -87.0f);
    float z = x * 1.4426950408889634f;
    float t = z + 12582912.0f;
    float fi = t - 12582912.0f;
    float f = z - fi;
    int  i  = __float_as_int(t) - 0x4B400000;
    float p = 1.3333558e-3f;
    p = fmaf(p, f, 9.6181291e-3f);
    p = fmaf(p, f, 5.5504109e-2f);
    p = fmaf(p, f, 2.4022651e-1f);
    p = fmaf(p, f, 6.9314718e-1f);
    p = fmaf(p, f, 1.0f);
    return __int_as_float(__float_as_int(p) + (i << 23));
}

__device__ __forceinline__ uint32_t f22bf(float2 v) {
    __nv_bfloat162 b = __float22bfloat162_rn(v);
    return *reinterpret_cast<uint32_t*>(&b);
}

// ---------------- main: R4 mainloop, 2-buffer depth-2 prefetch, 4 CTAs/SM -------------
// Buffer buf[kk&1] is consumed (converted to bf16 fragments) and immediately reloaded
// with chunk kk+2: depth-2 pipelining with only 16 buffer registers. launch_bounds
// (256,4) caps regs at 64 -> 32 warps/SM for latency hiding.
__global__ void __launch_bounds__(256, 4)
vmf_main(const float* __restrict__ x,
         float* __restrict__ out_llh,
         float* __restrict__ out_lp,
         int N) {
    __shared__ __align__(16) __nv_bfloat16 smu[K_COMP][MU_PAD];
    __shared__ float s_kappa[K_COMP], s_logC[K_COMP], s_la[K_COMP], s_C2[K_COMP];

    int tid = threadIdx.x;

    // stage mu with k-pair permutation (smem slot i <- phys pair (i<4 ? 2i : 2i-7))
    const uint32_t* gmu32 = reinterpret_cast<const uint32_t*>(g_mu);
    for (int idx = tid; idx < K_COMP * (DDIM / 2); idx += 256) {
        int kk = idx >> 7;
        int dp = idx & 127;
        int i  = dp & 7;
        int srcp = (i < 4) ? (2 * i) : (2 * i - 7);
        int src  = (dp & ~7) | srcp;
        reinterpret_cast<uint32_t*>(&smu[kk][0])[dp] = gmu32[kk * 128 + src];
    }
    if (tid < K_COMP) {
        s_kappa[tid] = g_kappa[tid];
        s_logC[tid]  = g_logC[tid];
        s_la[tid]    = g_la[tid];
        s_C2[tid]    = g_C2[tid];
    }
    __syncthreads();

    int warp = tid >> 5, lane = tid & 31;
    int row0 = blockIdx.x * 128 + warp * 16;

    int r  = lane >> 2;        // 0..7
    int cq = (lane & 3) * 2;   // logical col-pair base

    const float* p0 = x + (size_t)(row0 + r) * DDIM + (lane & 3) * 4;
    const float* p1 = p0 + 8 * DDIM;

    // ldmatrix B lane address (reads permuted smu)
    uint32_t smu_base = (uint32_t)__cvta_generic_to_shared(&smu[0][0]);
    int li   = lane & 7;
    int csel = (lane >> 3) & 1;
    int tsel = (lane >> 4) & 1;
    uint32_t lm_base = smu_base + (uint32_t)(((li + tsel * 8) * MU_PAD + csel * 8) * 2);

    float acc[8][4];
#pragma unroll
    for (int t = 0; t < 8; t++)
#pragma unroll
        for (int j = 0; j < 4; j++) acc[t][j] = 0.0f;

    // 2-buffer depth-2 prefetch
    float4 buf[2][2];
#pragma unroll
    for (int g = 0; g < 2; g++) {
        buf[g][0] = __ldcs(reinterpret_cast<const float4*>(p0 + g * 16));
        buf[g][1] = __ldcs(reinterpret_cast<const float4*>(p1 + g * 16));
    }

#pragma unroll
    for (int kk = 0; kk < 16; kk++) {
        int b = kk & 1;
        float4 A0 = buf[b][0], A1 = buf[b][1];
        uint32_t fa0 = f22bf(make_float2(A0.x, A0.y));
        uint32_t fa2 = f22bf(make_float2(A0.z, A0.w));
        uint32_t fa1 = f22bf(make_float2(A1.x, A1.y));
        uint32_t fa3 = f22bf(make_float2(A1.z, A1.w));

        // buf[b] now dead -> reload with chunk kk+2 (keeps 2 chunks in flight)
        if (kk < 14) {
            int off = (kk + 2) * 16;
            buf[b][0] = __ldcs(reinterpret_cast<const float4*>(p0 + off));
            buf[b][1] = __ldcs(reinterpret_cast<const float4*>(p1 + off));
        }

        uint32_t lmaddr = lm_base + (uint32_t)(kk * 32);
#pragma unroll
        for (int tp = 0; tp < 4; tp++) {
            uint32_t b0, b1, b2, b3;
            asm volatile(
                "ldmatrix.sync.aligned.m8n8.x4.shared.b16 {%0,%1,%2,%3}, [%4];\n"
                : "=r"(b0), "=r"(b1), "=r"(b2), "=r"(b3)
                : "r"(lmaddr + (uint32_t)(tp * 16 * MU_PAD * 2)));
            asm volatile(
                "mma.sync.aligned.m16n8k16.row.col.f32.bf16.bf16.f32 "
                "{%0,%1,%2,%3}, {%4,%5,%6,%7}, {%8,%9}, {%0,%1,%2,%3};\n"
                : "+f"(acc[tp*2][0]), "+f"(acc[tp*2][1]), "+f"(acc[tp*2][2]), "+f"(acc[tp*2][3])
                : "r"(fa0), "r"(fa1), "r"(fa2), "r"(fa3), "r"(b0), "r"(b1));
            asm volatile(
                "mma.sync.aligned.m16n8k16.row.col.f32.bf16.bf16.f32 "
                "{%0,%1,%2,%3}, {%4,%5,%6,%7}, {%8,%9}, {%0,%1,%2,%3};\n"
                : "+f"(acc[tp*2+1][0]), "+f"(acc[tp*2+1][1]), "+f"(acc[tp*2+1][2]), "+f"(acc[tp*2+1][3])
                : "r"(fa0), "r"(fa1), "r"(fa2), "r"(fa3), "r"(b2), "r"(b3));
        }
    }

    // ---- epilogue: log_prob + per-row logsumexp (R4 form, direct stores) ----
    int gr0 = row0 + r, gr1 = gr0 + 8;
    float2* lp0 = reinterpret_cast<float2*>(out_lp + (size_t)gr0 * K_COMP);
    float2* lp1 = reinterpret_cast<float2*>(out_lp + (size_t)gr1 * K_COMP);

    float m0 = -1e30f, m1 = -1e30f;
#pragma unroll
    for (int t = 0; t < 8; t++) {
        int cc = t * 8 + cq;
        float k0 = s_kappa[cc], k1 = s_kappa[cc + 1];
        float lc0 = s_logC[cc], lc1 = s_logC[cc + 1];
        float la0 = s_la[cc],   la1 = s_la[cc + 1];
        float lp00 = fmaf(k0, acc[t][0], lc0);
        float lp01 = fmaf(k1, acc[t][1], lc1);
        float lp10 = fmaf(k0, acc[t][2], lc0);
        float lp11 = fmaf(k1, acc[t][3], lc1);
        __stcs(lp0 + (cc >> 1), make_float2(lp00, lp01));
        __stcs(lp1 + (cc >> 1), make_float2(lp10, lp11));
        m0 = fmaxf(m0, fmaxf(lp00 + la0, lp01 + la1));
        m1 = fmaxf(m1, fmaxf(lp10 + la0, lp11 + la1));
    }
    m0 = fmaxf(m0, __shfl_xor_sync(0xffffffffu, m0, 1));
    m0 = fmaxf(m0, __shfl_xor_sync(0xffffffffu, m0, 2));
    m1 = fmaxf(m1, __shfl_xor_sync(0xffffffffu, m1, 1));
    m1 = fmaxf(m1, __shfl_xor_sync(0xffffffffu, m1, 2));

    float s0 = 0.0f, s1 = 0.0f;
#pragma unroll
    for (int t = 0; t < 8; t++) {
        int cc = t * 8 + cq;
        float k0 = s_kappa[cc], k1 = s_kappa[cc + 1];
        float c20 = s_C2[cc],   c21 = s_C2[cc + 1];
        s0 += fexp(fmaf(k0, acc[t][0], c20) - m0);
        s0 += fexp(fmaf(k1, acc[t][1], c21) - m0);
        s1 += fexp(fmaf(k0, acc[t][2], c20) - m1);
        s1 += fexp(fmaf(k1, acc[t][3], c21) - m1);
    }
    s0 += __shfl_xor_sync(0xffffffffu, s0, 1);
    s0 += __shfl_xor_sync(0xffffffffu, s0, 2);
    s1 += __shfl_xor_sync(0xffffffffu, s1, 1);
    s1 += __shfl_xor_sync(0xffffffffu, s1, 2);

    if ((lane & 3) == 0) {
        out_llh[gr0] = m0 + __logf(s0);
        out_llh[gr1] = m1 + __logf(s1);
    }
}

// ---------------- launch -----------------------------------------------------------
extern "C" void kernel_launch(void* const* d_in, const int* in_sizes, int n_in,
                              void* d_out, int out_size) {
    const float* x           = (const float*)d_in[0];
    const float* alpha_logit = (const float*)d_in[1];
    const float* mu_unnorm   = (const float*)d_in[2];
    const float* log_kappa   = (const float*)d_in[3];

    int K = in_sizes[1];            // 64
    int D = in_sizes[2] / K;        // 256
    int N = in_sizes[0] / D;        // 262144
    (void)K; (void)n_in; (void)out_size;

    float* out = (float*)d_out;
    float* llh = out;               // (N,)
    float* lp  = out + (size_t)N;   // (N, K) row-major

    prep_fast<<<1, 1024>>>(alpha_logit, mu_unnorm, log_kappa);
    vmf_main<<<N / 128, 256>>>(x, llh, lp, N);
}